// round 13
// baseline (speedup 1.0000x reference)
#include <cuda_runtime.h>
#include <cstdint>

typedef unsigned long long u64;
#define FULLMASK 0xffffffffu
static constexpr float EPSF = 1e-8f;

static constexpr int NS = 3;                     // pipeline stages
static constexpr int AREAS_PER_TILE = 64;        // 64 areas * 256B = 16KB
static constexpr int TILE_BYTES = AREAS_PER_TILE * 64 * 4;
static constexpr int STAGE_OFF = 1024;           // barriers live below
static constexpr int SMEM_TOTAL = STAGE_OFF + NS * 2 * TILE_BYTES;  // 99328

// ---------- packed f32x2 helpers (sm_103a) ----------
__device__ __forceinline__ u64 pk2(float lo, float hi) {
    u64 d; asm("mov.b64 %0,{%1,%2};" : "=l"(d) : "f"(lo), "f"(hi)); return d;
}
__device__ __forceinline__ float2 upk2(u64 v) {
    float2 o; asm("mov.b64 {%0,%1},%2;" : "=f"(o.x), "=f"(o.y) : "l"(v)); return o;
}
__device__ __forceinline__ u64 fma2_(u64 a, u64 b, u64 c) {
    u64 d; asm("fma.rn.f32x2 %0,%1,%2,%3;" : "=l"(d) : "l"(a), "l"(b), "l"(c)); return d;
}
__device__ __forceinline__ u64 mul2_(u64 a, u64 b) {
    u64 d; asm("mul.rn.f32x2 %0,%1,%2;" : "=l"(d) : "l"(a), "l"(b)); return d;
}
__device__ __forceinline__ u64 add2_(u64 a, u64 b) {
    u64 d; asm("add.rn.f32x2 %0,%1,%2;" : "=l"(d) : "l"(a), "l"(b)); return d;
}
__device__ __forceinline__ u64 splat2(float c) { return pk2(c, c); }
__device__ __forceinline__ float rcp_approx(float x) {
    float r; asm("rcp.approx.f32 %0, %1;" : "=f"(r) : "f"(x)); return r;
}
__device__ __forceinline__ u64 shfl_add2(u64 v, int off) {
    float2 s = upk2(v);
    float ax = __shfl_xor_sync(FULLMASK, s.x, off);
    float ay = __shfl_xor_sync(FULLMASK, s.y, off);
    return add2_(v, pk2(ax, ay));
}

// ---------- mbarrier / TMA helpers ----------
__device__ __forceinline__ uint32_t smem_u32(const void* p) {
    uint32_t a;
    asm("{ .reg .u64 t; cvta.to.shared.u64 t, %1; cvt.u32.u64 %0, t; }" : "=r"(a) : "l"(p));
    return a;
}
__device__ __forceinline__ void mbar_init(uint32_t m, uint32_t cnt) {
    asm volatile("mbarrier.init.shared.b64 [%0], %1;" :: "r"(m), "r"(cnt) : "memory");
}
__device__ __forceinline__ void mbar_expect_tx(uint32_t m, uint32_t bytes) {
    asm volatile("mbarrier.arrive.expect_tx.shared.b64 _, [%0], %1;" :: "r"(m), "r"(bytes) : "memory");
}
__device__ __forceinline__ void mbar_arrive(uint32_t m) {
    asm volatile("mbarrier.arrive.shared.b64 _, [%0];" :: "r"(m) : "memory");
}
__device__ __forceinline__ void mbar_wait(uint32_t m, uint32_t parity) {
    asm volatile(
        "{\n\t.reg .pred P;\n\t"
        "LW_%=:\n\t"
        "mbarrier.try_wait.parity.acquire.cta.shared::cta.b64 P, [%0], %1, 0x989680;\n\t"
        "@P bra.uni LD_%=;\n\t"
        "bra.uni LW_%=;\n\t"
        "LD_%=:\n\t}"
        :: "r"(m), "r"(parity) : "memory");
}
__device__ __forceinline__ void bulk_g2s(uint32_t dst, const void* src,
                                         uint32_t bytes, uint32_t mbar) {
    asm volatile(
        "cp.async.bulk.shared::cta.global.mbarrier::complete_tx::bytes [%0], [%1], %2, [%3];"
        :: "r"(dst), "l"(src), "r"(bytes), "r"(mbar) : "memory");
}

// g(r) = r - sin(2*pi*r)/(2*pi), odd Taylor to r^11 on [-0.5,0.5].
__device__ __forceinline__ u64 gpoly2(u64 r) {
    u64 z = mul2_(r, r);
    u64 p =            splat2(  2.4023870f);
    p = fma2_(p, z, splat2( -6.6938470f));
    p = fma2_(p, z, splat2( 12.2081128f));
    p = fma2_(p, z, splat2(-12.9878788f));
    p = fma2_(p, z, splat2(  6.5797363f));
    return mul2_(mul2_(p, z), r);
}
__device__ __forceinline__ void mask2(float4 mv, u64& m01, u64& m23) {
    float n0 = rintf(mv.x), n1 = rintf(mv.y), n2 = rintf(mv.z), n3 = rintf(mv.w);
    u64 r01 = pk2(mv.x - n0, mv.y - n1);
    u64 r23 = pk2(mv.z - n2, mv.w - n3);
    m01 = add2_(gpoly2(gpoly2(r01)), pk2(n0, n1));
    m23 = add2_(gpoly2(gpoly2(r23)), pk2(n2, n3));
}

__global__ void zero_out_kernel(float* out, int n) {
    int i = blockIdx.x * blockDim.x + threadIdx.x;
    if (i < n) out[i] = 0.0f;
}

// One quad (4 areas) for this lane; accumulates into acc2.
__device__ __forceinline__ void do_quad(
    float4 iv0, float4 iv1, float4 mv0, float4 mv1, u64& acc2)
{
    u64 m01, m23, m45, m67;
    mask2(mv0, m01, m23);
    mask2(mv1, m45, m67);

    u64 t01 = mul2_(pk2(iv0.x, iv0.y), m01);
    u64 t23 = mul2_(pk2(iv0.z, iv0.w), m23);
    u64 t45 = mul2_(pk2(iv1.x, iv1.y), m45);
    u64 t67 = mul2_(pk2(iv1.z, iv1.w), m67);

    u64 u01 = mul2_(m01, t01), u23 = mul2_(m23, t23);
    u64 u45 = mul2_(m45, t45), u67 = mul2_(m67, t67);

    u64 A2 = mul2_(u01, u01);
    A2 = fma2_(u23, u23, A2); A2 = fma2_(u45, u45, A2); A2 = fma2_(u67, u67, A2);
    u64 B2 = mul2_(m01, u01);
    B2 = fma2_(m23, u23, B2); B2 = fma2_(m45, u45, B2); B2 = fma2_(m67, u67, B2);
    u64 C2 = mul2_(m01, m01);
    C2 = fma2_(m23, m23, C2); C2 = fma2_(m45, m45, C2); C2 = fma2_(m67, m67, C2);

    float2 pm = upk2(add2_(add2_(m01, m23), add2_(m45, m67)));
    float2 pt = upk2(add2_(add2_(t01, t23), add2_(t45, t67)));
    u64 red = pk2(pm.x + pm.y, pt.x + pt.y);
    red = shfl_add2(red, 4);
    red = shfl_add2(red, 2);
    red = shfl_add2(red, 1);
    float2 sums = upk2(red);

    float rinv = rcp_approx(sums.x + EPSF);
    float mean = sums.y * rinv;

    u64 w2 = fma2_(splat2(mean), C2, mul2_(splat2(-2.0f), B2));
    u64 c2 = fma2_(splat2(mean), w2, A2);
    acc2 = fma2_(c2, splat2(rinv), acc2);
}

// TMA-staged streaming: 3-stage smem ring of 16KB img + 16KB msk tiles.
// Producer = thread 0 (bulk copies); consumers = all 8 warps via LDS.128.
__global__ __launch_bounds__(256) void area_loss_kernel(
    const float* __restrict__ img,
    const float* __restrict__ msk,
    float* __restrict__ out,
    int nAreas, float invTotal)
{
    extern __shared__ char smem[];
    __shared__ float bsum;

    const int tid  = threadIdx.x;
    const int lane = tid & 31;
    const int wib  = tid >> 5;          // warp in block (0..7)
    const int q    = lane & 7;          // lane within octet
    const int oct  = lane >> 3;         // area-of-quad within warp

    if (tid == 0) bsum = 0.0f;

    const uint32_t smem_base = smem_u32(smem);
    const uint32_t mbar_base = smem_base;          // full[s] at s*16, empty at +8
    auto fullb  = [&](int s) { return mbar_base + s * 16; };
    auto emptyb = [&](int s) { return mbar_base + s * 16 + 8; };

    const int nTiles = nAreas / AREAS_PER_TILE;
    // tiles for this block: t = blockIdx.x + k*gridDim.x
    int myTiles = 0;
    for (int t = blockIdx.x; t < nTiles; t += gridDim.x) myTiles++;

    if (tid == 0) {
        #pragma unroll
        for (int s = 0; s < NS; s++) {
            mbar_init(fullb(s), 1);
            mbar_init(emptyb(s), 256);
        }
    }
    __syncthreads();

    // prologue: fill first NS stages
    if (tid == 0) {
        int pn = myTiles < NS ? myTiles : NS;
        for (int k = 0; k < pn; k++) {
            const int t = blockIdx.x + k * gridDim.x;
            const int s = k % NS;
            mbar_expect_tx(fullb(s), 2 * TILE_BYTES);
            bulk_g2s(smem_base + STAGE_OFF + s * TILE_BYTES,
                     img + (size_t)t * (AREAS_PER_TILE * 64), TILE_BYTES, fullb(s));
            bulk_g2s(smem_base + STAGE_OFF + (NS + s) * TILE_BYTES,
                     msk + (size_t)t * (AREAS_PER_TILE * 64), TILE_BYTES, fullb(s));
        }
    }

    u64 acc2 = 0;

    for (int k = 0; k < myTiles; k++) {
        const int s = k % NS;
        const int u = k / NS;
        mbar_wait(fullb(s), u & 1);

        const float4* simg = (const float4*)(smem + STAGE_OFF + s * TILE_BYTES);
        const float4* smsk = (const float4*)(smem + STAGE_OFF + (NS + s) * TILE_BYTES);

        // warp wib handles quads 2*wib and 2*wib+1 of this 16-quad tile
        #pragma unroll
        for (int j = 0; j < 2; j++) {
            const int a   = 4 * (2 * wib + j) + oct;   // area in [0,64)
            const int idx = a * 16 + q;                // float4 units
            do_quad(simg[idx], simg[idx + 8], smsk[idx], smsk[idx + 8], acc2);
        }

        mbar_arrive(emptyb(s));

        // producer refills this stage for tile k+NS
        if (tid == 0) {
            const int kn = k + NS;
            if (kn < myTiles) {
                const int t  = blockIdx.x + kn * gridDim.x;
                const int sn = kn % NS;        // == s
                const int un = kn / NS;        // >= 1
                mbar_wait(emptyb(sn), (un - 1) & 1);
                mbar_expect_tx(fullb(sn), 2 * TILE_BYTES);
                bulk_g2s(smem_base + STAGE_OFF + sn * TILE_BYTES,
                         img + (size_t)t * (AREAS_PER_TILE * 64), TILE_BYTES, fullb(sn));
                bulk_g2s(smem_base + STAGE_OFF + (NS + sn) * TILE_BYTES,
                         msk + (size_t)t * (AREAS_PER_TILE * 64), TILE_BYTES, fullb(sn));
            }
        }
    }

    // remainder areas (nAreas % 64), handled by block 0 straight from gmem
    const int remAreas = nAreas - nTiles * AREAS_PER_TILE;
    if (blockIdx.x == 0 && remAreas > 0) {
        const float4* img4 = (const float4*)img;
        const float4* msk4 = (const float4*)msk;
        const int remQuads = remAreas / 4;
        for (int qd = wib; qd < remQuads; qd += 8) {
            const int a   = nTiles * AREAS_PER_TILE + 4 * qd + oct;
            const int idx = a * 16 + q;
            do_quad(img4[idx], img4[idx + 8], msk4[idx], msk4[idx + 8], acc2);
        }
    }

    // epilogue: collapse packed lanes, full-warp butterfly, one atomic/block
    float2 ap = upk2(acc2);
    float acc = ap.x + ap.y;
    #pragma unroll
    for (int o = 16; o > 0; o >>= 1)
        acc += __shfl_xor_sync(FULLMASK, acc, o);
    if (lane == 0) atomicAdd(&bsum, acc);
    __syncthreads();
    if (tid == 0) atomicAdd(out, bsum * invTotal);
}

extern "C" void kernel_launch(void* const* d_in, const int* in_sizes, int n_in,
                              void* d_out, int out_size)
{
    const float* img = (const float*)d_in[0];     // sv_area_image
    const float* msk = (const float*)d_in[1];     // sv_area_mask
    float* out = (float*)d_out;

    const int nAreas = in_sizes[0] / 64;          // B*N areas of 8x8
    const float invTotal = 1.0f / (float)nAreas;

    zero_out_kernel<<<(out_size + 255) / 256, 256>>>(out, out_size);

    static bool attr_set = false;
    if (!attr_set) {
        cudaFuncSetAttribute(area_loss_kernel,
                             cudaFuncAttributeMaxDynamicSharedMemorySize, SMEM_TOTAL);
        attr_set = true;
    }
    // 2 blocks/SM (smem-limited), one exact wave
    area_loss_kernel<<<296, 256, SMEM_TOTAL>>>(img, msk, out, nAreas, invTotal);
}

// round 14
// speedup vs baseline: 1.4848x; 1.4848x over previous
#include <cuda_runtime.h>
#include <cstdint>

typedef unsigned long long u64;
#define FULLMASK 0xffffffffu
static constexpr float EPSF = 1e-8f;

static constexpr int D = 4;                       // per-warp pipeline depth (quads)
static constexpr int STAGE_BYTES = 2048;          // 1KB img + 1KB msk per quad
static constexpr int WARP_SMEM = D * STAGE_BYTES; // 8KB per warp
static constexpr int SMEM_TOTAL = 8 * WARP_SMEM;  // 64KB per block (8 warps)

// ---------- packed f32x2 helpers (sm_103a) ----------
__device__ __forceinline__ u64 pk2(float lo, float hi) {
    u64 d; asm("mov.b64 %0,{%1,%2};" : "=l"(d) : "f"(lo), "f"(hi)); return d;
}
__device__ __forceinline__ float2 upk2(u64 v) {
    float2 o; asm("mov.b64 {%0,%1},%2;" : "=f"(o.x), "=f"(o.y) : "l"(v)); return o;
}
__device__ __forceinline__ u64 fma2_(u64 a, u64 b, u64 c) {
    u64 d; asm("fma.rn.f32x2 %0,%1,%2,%3;" : "=l"(d) : "l"(a), "l"(b), "l"(c)); return d;
}
__device__ __forceinline__ u64 mul2_(u64 a, u64 b) {
    u64 d; asm("mul.rn.f32x2 %0,%1,%2;" : "=l"(d) : "l"(a), "l"(b)); return d;
}
__device__ __forceinline__ u64 add2_(u64 a, u64 b) {
    u64 d; asm("add.rn.f32x2 %0,%1,%2;" : "=l"(d) : "l"(a), "l"(b)); return d;
}
__device__ __forceinline__ u64 splat2(float c) { return pk2(c, c); }
__device__ __forceinline__ float rcp_approx(float x) {
    float r; asm("rcp.approx.f32 %0, %1;" : "=f"(r) : "f"(x)); return r;
}
__device__ __forceinline__ u64 shfl_add2(u64 v, int off) {
    float2 s = upk2(v);
    float ax = __shfl_xor_sync(FULLMASK, s.x, off);
    float ay = __shfl_xor_sync(FULLMASK, s.y, off);
    return add2_(v, pk2(ax, ay));
}

// ---------- cp.async helpers ----------
__device__ __forceinline__ uint32_t smem_u32(const void* p) {
    uint32_t a;
    asm("{ .reg .u64 t; cvta.to.shared.u64 t, %1; cvt.u32.u64 %0, t; }" : "=r"(a) : "l"(p));
    return a;
}
__device__ __forceinline__ void cp16(uint32_t dst, const void* src) {
    asm volatile("cp.async.cg.shared.global [%0], [%1], 16;" :: "r"(dst), "l"(src) : "memory");
}
__device__ __forceinline__ void cp_commit() {
    asm volatile("cp.async.commit_group;" ::: "memory");
}
template<int N> __device__ __forceinline__ void cp_wait() {
    asm volatile("cp.async.wait_group %0;" :: "n"(N) : "memory");
}

// g(r) = r - sin(2*pi*r)/(2*pi), odd Taylor to r^11 on [-0.5,0.5].
// diff_round(diff_round(x)) = rint(x) + g(g(x - rint(x))).
__device__ __forceinline__ u64 gpoly2(u64 r) {
    u64 z = mul2_(r, r);
    u64 p =            splat2(  2.4023870f);
    p = fma2_(p, z, splat2( -6.6938470f));
    p = fma2_(p, z, splat2( 12.2081128f));
    p = fma2_(p, z, splat2(-12.9878788f));
    p = fma2_(p, z, splat2(  6.5797363f));
    return mul2_(mul2_(p, z), r);
}
__device__ __forceinline__ void mask2(float4 mv, u64& m01, u64& m23) {
    float n0 = rintf(mv.x), n1 = rintf(mv.y), n2 = rintf(mv.z), n3 = rintf(mv.w);
    u64 r01 = pk2(mv.x - n0, mv.y - n1);
    u64 r23 = pk2(mv.z - n2, mv.w - n3);
    m01 = add2_(gpoly2(gpoly2(r01)), pk2(n0, n1));
    m23 = add2_(gpoly2(gpoly2(r23)), pk2(n2, n3));
}

__global__ void zero_out_kernel(float* out, int n) {
    int i = blockIdx.x * blockDim.x + threadIdx.x;
    if (i < n) out[i] = 0.0f;
}

// One quad (4 areas) of work for this lane; accumulates into acc2.
__device__ __forceinline__ void do_quad(
    float4 iv0, float4 iv1, float4 mv0, float4 mv1, u64& acc2)
{
    u64 m01, m23, m45, m67;
    mask2(mv0, m01, m23);
    mask2(mv1, m45, m67);

    u64 t01 = mul2_(pk2(iv0.x, iv0.y), m01);
    u64 t23 = mul2_(pk2(iv0.z, iv0.w), m23);
    u64 t45 = mul2_(pk2(iv1.x, iv1.y), m45);
    u64 t67 = mul2_(pk2(iv1.z, iv1.w), m67);

    u64 u01 = mul2_(m01, t01), u23 = mul2_(m23, t23);
    u64 u45 = mul2_(m45, t45), u67 = mul2_(m67, t67);

    u64 A2 = mul2_(u01, u01);
    A2 = fma2_(u23, u23, A2); A2 = fma2_(u45, u45, A2); A2 = fma2_(u67, u67, A2);
    u64 B2 = mul2_(m01, u01);
    B2 = fma2_(m23, u23, B2); B2 = fma2_(m45, u45, B2); B2 = fma2_(m67, u67, B2);
    u64 C2 = mul2_(m01, m01);
    C2 = fma2_(m23, m23, C2); C2 = fma2_(m45, m45, C2); C2 = fma2_(m67, m67, C2);

    float2 pm = upk2(add2_(add2_(m01, m23), add2_(m45, m67)));
    float2 pt = upk2(add2_(add2_(t01, t23), add2_(t45, t67)));
    u64 red = pk2(pm.x + pm.y, pt.x + pt.y);
    red = shfl_add2(red, 4);
    red = shfl_add2(red, 2);
    red = shfl_add2(red, 1);
    float2 sums = upk2(red);

    float rinv = rcp_approx(sums.x + EPSF);
    float mean = sums.y * rinv;

    u64 w2 = fma2_(splat2(mean), C2, mul2_(splat2(-2.0f), B2));
    u64 c2 = fma2_(splat2(mean), w2, A2);
    acc2 = fma2_(c2, splat2(rinv), acc2);
}

// Issue all copies for one quad into stage s of this warp's smem region.
__device__ __forceinline__ void issue_quad(
    uint32_t wbase, int s,
    const float4* __restrict__ img4, const float4* __restrict__ msk4,
    int qb /* quad*64 in float4 units */, int lane)
{
    const uint32_t si = wbase + s * STAGE_BYTES;
    const uint32_t sm = si + 1024;
    cp16(si + lane * 16,        img4 + qb + lane);
    cp16(si + (lane + 32) * 16, img4 + qb + lane + 32);
    cp16(sm + lane * 16,        msk4 + qb + lane);
    cp16(sm + (lane + 32) * 16, msk4 + qb + lane + 32);
    cp_commit();
}

// Per-warp cp.async pipeline, depth D quads. No cross-warp synchronization.
__global__ __launch_bounds__(256) void area_loss_kernel(
    const float4* __restrict__ img4,
    const float4* __restrict__ msk4,
    float* __restrict__ out,
    int nQuads, float invTotal)
{
    extern __shared__ char smem[];
    __shared__ float bsum;

    const int tid  = threadIdx.x;
    const int lane = tid & 31;
    const int wib  = tid >> 5;
    const int q    = lane & 7;
    const int oct  = lane >> 3;

    if (tid == 0) bsum = 0.0f;

    const uint32_t wbase = smem_u32(smem) + wib * WARP_SMEM;
    const char* wptr = smem + wib * WARP_SMEM;

    const int gw = (blockIdx.x * blockDim.x + tid) >> 5;     // global warp id
    const int tw = (gridDim.x * blockDim.x) >> 5;            // total warps

    int my = 0;
    if (gw < nQuads) my = (nQuads - gw - 1) / tw + 1;

    // prologue: fill up to D stages
    const int pro = my < D ? my : D;
    for (int j = 0; j < pro; j++)
        issue_quad(wbase, j, img4, msk4, (gw + j * tw) * 64, lane);

    u64 acc2 = 0;

    for (int j = 0; j < my; j++) {
        // group j must be complete; deep-pipe wait unless near the tail
        if (j + (D - 1) < my) cp_wait<D - 1>(); else cp_wait<0>();
        __syncwarp();

        const int s = j % D;
        const float4* si = (const float4*)(wptr + s * STAGE_BYTES);
        const float4* sm = si + 64;                          // +1024B
        const int idx = oct * 16 + q;
        do_quad(si[idx], si[idx + 8], sm[idx], sm[idx + 8], acc2);

        __syncwarp();                                        // all reads done before refill
        const int jn = j + D;
        if (jn < my)
            issue_quad(wbase, s, img4, msk4, (gw + jn * tw) * 64, lane);
    }

    // epilogue: collapse packed lanes, full-warp butterfly, one atomic/block
    float2 ap = upk2(acc2);
    float acc = ap.x + ap.y;
    #pragma unroll
    for (int o = 16; o > 0; o >>= 1)
        acc += __shfl_xor_sync(FULLMASK, acc, o);
    if (lane == 0) atomicAdd(&bsum, acc);
    __syncthreads();
    if (tid == 0) atomicAdd(out, bsum * invTotal);
}

extern "C" void kernel_launch(void* const* d_in, const int* in_sizes, int n_in,
                              void* d_out, int out_size)
{
    const float4* img4 = (const float4*)d_in[0];  // sv_area_image
    const float4* msk4 = (const float4*)d_in[1];  // sv_area_mask
    float* out = (float*)d_out;

    const int nAreas = in_sizes[0] / 64;          // B*N areas of 8x8
    const int nQuads = nAreas / 4;
    const float invTotal = 1.0f / (float)nAreas;

    zero_out_kernel<<<(out_size + 255) / 256, 256>>>(out, out_size);

    static bool attr_set = false;
    if (!attr_set) {
        cudaFuncSetAttribute(area_loss_kernel,
                             cudaFuncAttributeMaxDynamicSharedMemorySize, SMEM_TOTAL);
        attr_set = true;
    }
    // 2 blocks/SM (smem: 2 x 64KB), one exact wave on 148 SMs
    area_loss_kernel<<<296, 256, SMEM_TOTAL>>>(img4, msk4, out, nQuads, invTotal);
}